// round 16
// baseline (speedup 1.0000x reference)
#include <cuda_runtime.h>
#include <cuda_bf16.h>
#include <cuda_fp16.h>
#include <cstdint>

#define VNUM 50000
#define OUTD 128
#define EMAX 1600000
#define EPS_F 1e-7f
#define PADK 136                       // padded k-stride (bf16 elems); 272B rows -> LDSM conflict-free

// ---------------------------------------------------------------------------
// Device-global scratch (no runtime allocation allowed).
// ---------------------------------------------------------------------------
__device__ float g_ptr[(size_t)VNUM * OUTD];   // segment-sum result (25.6 MB)
__device__ int   g_deg[VNUM];
__device__ int   g_off[VNUM + 1];
__device__ int   g_cursor[VNUM];
__device__ int2  g_sw[EMAX];                   // packed (sidx, bitcast(weight))
__device__ __align__(16) __half g_vrh[(size_t)VNUM * OUTD];  // fp16 vrepr (12.8 MB)
// B = [loc_w ; std_w] as 256 rows x 128 k, bf16 hi/lo, row-major.
__device__ __align__(16) __nv_bfloat16 g_Bhi[256 * 128];
__device__ __align__(16) __nv_bfloat16 g_Blo[256 * 128];

// ---------------------------------------------------------------------------
// mma.sync m16n8k16 bf16 + ldmatrix (baseline sm_75/80 PTX)
// ---------------------------------------------------------------------------
__device__ __forceinline__ void mma16816(float* c, const uint32_t* a, const uint32_t* b) {
    asm volatile(
        "mma.sync.aligned.m16n8k16.row.col.f32.bf16.bf16.f32 "
        "{%0,%1,%2,%3}, {%4,%5,%6,%7}, {%8,%9}, {%0,%1,%2,%3};"
        : "+f"(c[0]), "+f"(c[1]), "+f"(c[2]), "+f"(c[3])
        : "r"(a[0]), "r"(a[1]), "r"(a[2]), "r"(a[3]), "r"(b[0]), "r"(b[1]));
}
__device__ __forceinline__ void ldsm_x4(uint32_t* r, uint32_t addr) {
    asm volatile(
        "ldmatrix.sync.aligned.m8n8.x4.shared.b16 {%0,%1,%2,%3}, [%4];"
        : "=r"(r[0]), "=r"(r[1]), "=r"(r[2]), "=r"(r[3]) : "r"(addr));
}

// ---------------------------------------------------------------------------
// Kernel 1: zero degree counters
// ---------------------------------------------------------------------------
__global__ void zero_deg_kernel() {
    int i = blockIdx.x * blockDim.x + threadIdx.x;
    if (i < VNUM) g_deg[i] = 0;
}

// ---------------------------------------------------------------------------
// Kernel 2: count edges per target, 8 edges per thread (2x int4, MLP=8)
// ---------------------------------------------------------------------------
__global__ void count_kernel(const int* __restrict__ tidx, int E) {
    int i = (blockIdx.x * blockDim.x + threadIdx.x) * 8;
    if (i + 7 < E) {
        int4 t0 = __ldg((const int4*)(tidx + i));
        int4 t1 = __ldg((const int4*)(tidx + i + 4));
        atomicAdd(&g_deg[t0.x], 1); atomicAdd(&g_deg[t0.y], 1);
        atomicAdd(&g_deg[t0.z], 1); atomicAdd(&g_deg[t0.w], 1);
        atomicAdd(&g_deg[t1.x], 1); atomicAdd(&g_deg[t1.y], 1);
        atomicAdd(&g_deg[t1.z], 1); atomicAdd(&g_deg[t1.w], 1);
    } else {
        for (int e = i; e < E; e++) atomicAdd(&g_deg[__ldg(tidx + e)], 1);
    }
}

// ---------------------------------------------------------------------------
// Kernel 3: exclusive scan -> g_off, g_cursor. One block, warp-shuffle scan.
// ---------------------------------------------------------------------------
__global__ void scan_kernel() {
    __shared__ int warp_tot[32];
    __shared__ int carry_sh;
    int tid  = threadIdx.x;
    int lane = tid & 31;
    int wid  = tid >> 5;
    if (tid == 0) carry_sh = 0;
    __syncthreads();

    for (int base = 0; base < VNUM; base += 1024) {
        int i = base + tid;
        int x = (i < VNUM) ? g_deg[i] : 0;

        int incl = x;
#pragma unroll
        for (int ofs = 1; ofs < 32; ofs <<= 1) {
            int v = __shfl_up_sync(0xffffffffu, incl, ofs);
            if (lane >= ofs) incl += v;
        }
        if (lane == 31) warp_tot[wid] = incl;
        __syncthreads();

        if (wid == 0) {
            int t = warp_tot[lane];
            int s = t;
#pragma unroll
            for (int ofs = 1; ofs < 32; ofs <<= 1) {
                int v = __shfl_up_sync(0xffffffffu, s, ofs);
                if (lane >= ofs) s += v;
            }
            warp_tot[lane] = s - t;
        }
        __syncthreads();

        int carry = carry_sh;
        int excl = carry + warp_tot[wid] + incl - x;
        if (i < VNUM) {
            g_off[i] = excl;
            g_cursor[i] = excl;
        }
        __syncthreads();
        if (tid == 1023) carry_sh = carry + warp_tot[31] + incl;
        __syncthreads();
    }
    if (tid == 0) g_off[VNUM] = carry_sh;
}

// ---------------------------------------------------------------------------
// Kernel 4: fill CSR slots, 8 edges per thread (vector loads, MLP=8)
// ---------------------------------------------------------------------------
__global__ void fill_kernel(const int* __restrict__ sidx,
                            const int* __restrict__ tidx,
                            const float* __restrict__ enorm,
                            const float* __restrict__ esgn,
                            int E) {
    int i = (blockIdx.x * blockDim.x + threadIdx.x) * 8;
    if (i + 7 < E) {
#pragma unroll
        for (int h = 0; h < 2; h++) {
            int base = i + h * 4;
            int4   s = __ldg((const int4*)(sidx + base));
            int4   t = __ldg((const int4*)(tidx + base));
            float4 n = __ldg((const float4*)(enorm + base));
            float4 g = __ldg((const float4*)(esgn + base));
            int p0 = atomicAdd(&g_cursor[t.x], 1);
            int p1 = atomicAdd(&g_cursor[t.y], 1);
            int p2 = atomicAdd(&g_cursor[t.z], 1);
            int p3 = atomicAdd(&g_cursor[t.w], 1);
            g_sw[p0] = make_int2(s.x, __float_as_int(n.x * g.x));
            g_sw[p1] = make_int2(s.y, __float_as_int(n.y * g.y));
            g_sw[p2] = make_int2(s.z, __float_as_int(n.z * g.z));
            g_sw[p3] = make_int2(s.w, __float_as_int(n.w * g.w));
        }
    } else {
        for (int e = i; e < E; e++) {
            int t = __ldg(tidx + e);
            int pos = atomicAdd(&g_cursor[t], 1);
            float w = __ldg(enorm + e) * __ldg(esgn + e);
            g_sw[pos] = make_int2(__ldg(sidx + e), __float_as_int(w));
        }
    }
}

// ---------------------------------------------------------------------------
// Kernel 5: split weights to bf16 hi/lo, row-major [256][128].
// ---------------------------------------------------------------------------
__global__ void wconv_kernel(const float* __restrict__ lw,
                             const float* __restrict__ sw) {
    int idx = blockIdx.x * blockDim.x + threadIdx.x;
    if (idx >= 256 * 128) return;
    int n = idx >> 7;
    int k = idx & 127;
    float w = (n < 128) ? lw[n * 128 + k] : sw[(n - 128) * 128 + k];
    __nv_bfloat16 hi = __float2bfloat16(w);
    __nv_bfloat16 lo = __float2bfloat16(w - __bfloat162float(hi));
    g_Bhi[idx] = hi;
    g_Blo[idx] = lo;
}

// ---------------------------------------------------------------------------
// Kernel 6: convert vrepr fp32 -> fp16 (halves gather traffic).
// ---------------------------------------------------------------------------
__global__ void vconv_kernel(const float* __restrict__ vrepr) {
    int i = blockIdx.x * blockDim.x + threadIdx.x;
    const int n4 = VNUM * OUTD / 4;
    if (i >= n4) return;
    float4 v = __ldg((const float4*)vrepr + i);
    __half2 h01 = __floats2half2_rn(v.x, v.y);
    __half2 h23 = __floats2half2_rn(v.z, v.w);
    uint2 p;
    p.x = *(uint32_t*)&h01;
    p.y = *(uint32_t*)&h23;
    *((uint2*)g_vrh + i) = p;
}

// ---------------------------------------------------------------------------
// Kernel 7: gather-aggregate v3. One warp per target row. NO scalar tail:
// invalid lanes carry (s=0, w=0.0) and contribute nothing, so every batch
// runs the full unrolled MLP-8 path. fp16 rows (256 B/edge), fp32 accum.
// ---------------------------------------------------------------------------
__global__ void gather_kernel() {
    int v = (blockIdx.x * blockDim.x + threadIdx.x) >> 5;
    int lane = threadIdx.x & 31;
    if (v >= VNUM) return;

    int beg = __ldg(&g_off[v]);
    int end = __ldg(&g_off[v + 1]);

    float4 acc = make_float4(0.f, 0.f, 0.f, 0.f);
    const uint2* vrh = (const uint2*)g_vrh;    // 32 uint2 per row (4 halves each)
    const unsigned FULL = 0xffffffffu;

    for (int base = beg; base < end; base += 32) {
        int n = end - base;                    // >0; may be <32 on last batch
        int2 rec = (lane < n) ? __ldg(&g_sw[base + lane]) : make_int2(0, 0);

#pragma unroll
        for (int j = 0; j < 32; j += 8) {
            int s[8]; float w[8]; uint2 p[8];
#pragma unroll
            for (int jj = 0; jj < 8; jj++) {
                s[jj] = __shfl_sync(FULL, rec.x, j + jj);
                w[jj] = __int_as_float(__shfl_sync(FULL, rec.y, j + jj));
            }
#pragma unroll
            for (int jj = 0; jj < 8; jj++)
                p[jj] = __ldg(vrh + (size_t)s[jj] * 32 + lane);
#pragma unroll
            for (int jj = 0; jj < 8; jj++) {
                float2 a01 = __half22float2(*(__half2*)&p[jj].x);
                float2 a23 = __half22float2(*(__half2*)&p[jj].y);
                acc.x += w[jj] * a01.x; acc.y += w[jj] * a01.y;
                acc.z += w[jj] * a23.x; acc.w += w[jj] * a23.y;
            }
        }
    }
    ((float4*)g_ptr)[(size_t)v * 32 + lane] = acc;
}

// ---------------------------------------------------------------------------
// Kernel 8: dual GEMM + bias + softplus via mma.sync bf16 3-split + ldmatrix.
//   D = Ahi*Bhi + Alo*Bhi + Ahi*Blo   (error ~2^-16)
// Block: 256 threads / 8 warps, 64 rows x 256 cols (N=256 = loc|std).
// ---------------------------------------------------------------------------
#define SM_AHI 0
#define SM_ALO (64 * PADK * 2)                     // 17408
#define SM_BHI (2 * 64 * PADK * 2)                 // 34816
#define SM_BLO (2 * 64 * PADK * 2 + 256 * PADK * 2)// 104448
#define GEMM_SMEM (2 * 64 * PADK * 2 + 2 * 256 * PADK * 2)  // 174080

__global__ void __launch_bounds__(256, 1)
gemm_kernel(const float* __restrict__ lb,
            const float* __restrict__ sb,
            float* __restrict__ out) {
    extern __shared__ __align__(16) uint8_t smem[];
    __nv_bfloat16* shAhi = (__nv_bfloat16*)(smem + SM_AHI);
    __nv_bfloat16* shAlo = (__nv_bfloat16*)(smem + SM_ALO);
    __nv_bfloat16* shBhi = (__nv_bfloat16*)(smem + SM_BHI);
    __nv_bfloat16* shBlo = (__nv_bfloat16*)(smem + SM_BLO);

    int tid = threadIdx.x;
    int row0 = blockIdx.x * 64;

    // Stage A: read fp32 g_ptr, split into bf16 hi/lo.
    for (int i = tid; i < 2048; i += 256) {
        int r = i >> 5;
        int c4 = i & 31;
        int row = row0 + r;
        float4 v = (row < VNUM) ? __ldg((const float4*)g_ptr + (size_t)row * 32 + c4)
                                : make_float4(0.f, 0.f, 0.f, 0.f);
        __nv_bfloat16 h0 = __float2bfloat16(v.x), h1 = __float2bfloat16(v.y);
        __nv_bfloat16 h2 = __float2bfloat16(v.z), h3 = __float2bfloat16(v.w);
        __nv_bfloat16 l0 = __float2bfloat16(v.x - __bfloat162float(h0));
        __nv_bfloat16 l1 = __float2bfloat16(v.y - __bfloat162float(h1));
        __nv_bfloat16 l2 = __float2bfloat16(v.z - __bfloat162float(h2));
        __nv_bfloat16 l3 = __float2bfloat16(v.w - __bfloat162float(h3));
        uint2 hp, lp;
        hp.x = (uint32_t)__bfloat16_as_ushort(h0) | ((uint32_t)__bfloat16_as_ushort(h1) << 16);
        hp.y = (uint32_t)__bfloat16_as_ushort(h2) | ((uint32_t)__bfloat16_as_ushort(h3) << 16);
        lp.x = (uint32_t)__bfloat16_as_ushort(l0) | ((uint32_t)__bfloat16_as_ushort(l1) << 16);
        lp.y = (uint32_t)__bfloat16_as_ushort(l2) | ((uint32_t)__bfloat16_as_ushort(l3) << 16);
        *(uint2*)(shAhi + r * PADK + c4 * 4) = hp;
        *(uint2*)(shAlo + r * PADK + c4 * 4) = lp;
    }
    // Stage B: 256 rows x 16 uint4 (8 bf16 each) per matrix.
    for (int i = tid; i < 4096; i += 256) {
        int n = i >> 4;
        int c8 = i & 15;
        *(uint4*)(shBhi + n * PADK + c8 * 8) = *((const uint4*)g_Bhi + (size_t)n * 16 + c8);
        *(uint4*)(shBlo + n * PADK + c8 * 8) = *((const uint4*)g_Blo + (size_t)n * 16 + c8);
    }
    __syncthreads();

    int warp = tid >> 5;
    int lane = tid & 31;
    int warp_m = warp & 3;         // 4 m-tiles of 16 rows
    int col_half = warp >> 2;      // 0..1
    int g = lane >> 2;
    int tg = lane & 3;

    // ldmatrix lane address selectors
    int grp = lane >> 3;           // 0..3
    int r8  = lane & 7;            // row within 8x8 matrix
    // A x4: matrices {m0-7@k0, m8-15@k0, m0-7@k0+8, m8-15@k0+8}
    int a_row = warp_m * 16 + (grp & 1) * 8 + r8;
    int a_kof = (grp & 2) ? 8 : 0;
    uint32_t aHiAddr = (uint32_t)__cvta_generic_to_shared(shAhi + a_row * PADK + a_kof);
    uint32_t aLoAddr = (uint32_t)__cvta_generic_to_shared(shAlo + a_row * PADK + a_kof);
    // B x4 per n-pair: matrices {n0-7@k0, n0-7@k0+8, n8-15@k0, n8-15@k0+8}
    int b_rowsel = (grp & 2) * 4 + r8;     // 0..7 or 8..15
    int b_kof = (grp & 1) * 8;
    uint32_t bHiBase = (uint32_t)__cvta_generic_to_shared(shBhi) ;
    uint32_t bLoBase = (uint32_t)__cvta_generic_to_shared(shBlo) ;

    float acc[16][4];
#pragma unroll
    for (int t = 0; t < 16; t++)
        acc[t][0] = acc[t][1] = acc[t][2] = acc[t][3] = 0.f;

#pragma unroll
    for (int ks = 0; ks < 8; ks++) {
        uint32_t kbyte = (uint32_t)(ks * 16 * 2);
        uint32_t ah[4], al[4];
        ldsm_x4(ah, aHiAddr + kbyte);
        ldsm_x4(al, aLoAddr + kbyte);

#pragma unroll
        for (int pr = 0; pr < 8; pr++) {
            int n0 = col_half * 128 + pr * 16;
            uint32_t boff = (uint32_t)(((n0 + b_rowsel) * PADK + b_kof) * 2) + kbyte;
            uint32_t bh[4], bl[4];
            ldsm_x4(bh, bHiBase + boff);
            ldsm_x4(bl, bLoBase + boff);
            mma16816(acc[2 * pr],     ah, bh);       // bh[0],bh[1]
            mma16816(acc[2 * pr],     al, bh);
            mma16816(acc[2 * pr],     ah, bl);
            mma16816(acc[2 * pr + 1], ah, bh + 2);   // bh[2],bh[3]
            mma16816(acc[2 * pr + 1], al, bh + 2);
            mma16816(acc[2 * pr + 1], ah, bl + 2);
        }
    }

    int row_a = row0 + warp_m * 16 + g;
    int row_b = row_a + 8;
    float* out_loc = out;
    float* out_std = out + (size_t)VNUM * OUTD;

#pragma unroll
    for (int nt = 0; nt < 16; nt++) {
        int ncol = col_half * 128 + nt * 8 + tg * 2;
        if (ncol < 128) {
            float b0 = __ldg(lb + ncol), b1 = __ldg(lb + ncol + 1);
            if (row_a < VNUM) {
                float2 o = make_float2(acc[nt][0] + b0, acc[nt][1] + b1);
                *(float2*)(out_loc + (size_t)row_a * OUTD + ncol) = o;
            }
            if (row_b < VNUM) {
                float2 o = make_float2(acc[nt][2] + b0, acc[nt][3] + b1);
                *(float2*)(out_loc + (size_t)row_b * OUTD + ncol) = o;
            }
        } else {
            int sc = ncol - 128;
            float b0 = __ldg(sb + sc), b1 = __ldg(sb + sc + 1);
            if (row_a < VNUM) {
                float x0 = acc[nt][0] + b0, x1 = acc[nt][1] + b1;
                float2 o;
                o.x = fmaxf(x0, 0.f) + log1pf(expf(-fabsf(x0))) + EPS_F;
                o.y = fmaxf(x1, 0.f) + log1pf(expf(-fabsf(x1))) + EPS_F;
                *(float2*)(out_std + (size_t)row_a * OUTD + sc) = o;
            }
            if (row_b < VNUM) {
                float x0 = acc[nt][2] + b0, x1 = acc[nt][3] + b1;
                float2 o;
                o.x = fmaxf(x0, 0.f) + log1pf(expf(-fabsf(x0))) + EPS_F;
                o.y = fmaxf(x1, 0.f) + log1pf(expf(-fabsf(x1))) + EPS_F;
                *(float2*)(out_std + (size_t)row_b * OUTD + sc) = o;
            }
        }
    }
}

// ---------------------------------------------------------------------------
// Launch. Inputs: sidx, tidx, enorm, esgn, vrepr, loc_w, loc_b, std_w, std_b
// Output: [loc (VNUM*128), std (VNUM*128)] fp32
// ---------------------------------------------------------------------------
extern "C" void kernel_launch(void* const* d_in, const int* in_sizes, int n_in,
                              void* d_out, int out_size) {
    const int*   sidx  = (const int*)d_in[0];
    const int*   tidx  = (const int*)d_in[1];
    const float* enorm = (const float*)d_in[2];
    const float* esgn  = (const float*)d_in[3];
    const float* vrepr = (const float*)d_in[4];
    const float* lw    = (const float*)d_in[5];
    const float* lb    = (const float*)d_in[6];
    const float* sw    = (const float*)d_in[7];
    const float* sb    = (const float*)d_in[8];
    float* out = (float*)d_out;
    int E = in_sizes[0];
    if (E > EMAX) E = EMAX;

    (void)cudaFuncSetAttribute(gemm_kernel,
                               cudaFuncAttributeMaxDynamicSharedMemorySize, GEMM_SMEM);

    // 1) zero degree counters
    zero_deg_kernel<<<(VNUM + 255) / 256, 256>>>();
    // 2) count edges per target (8/thread)
    count_kernel<<<((E + 7) / 8 + 255) / 256, 256>>>(tidx, E);
    // 3) exclusive scan -> CSR offsets + cursors
    scan_kernel<<<1, 1024>>>();
    // 4) fill CSR (8/thread)
    fill_kernel<<<((E + 7) / 8 + 255) / 256, 256>>>(sidx, tidx, enorm, esgn, E);
    // 5) weights -> bf16 hi/lo
    wconv_kernel<<<(256 * 128 + 255) / 256, 256>>>(lw, sw);
    // 6) vrepr -> fp16
    vconv_kernel<<<(VNUM * OUTD / 4 + 255) / 256, 256>>>(vrepr);
    // 7) gather-aggregate (fp16 rows, no scalar tail) -> fp32 ptr
    gather_kernel<<<(VNUM * 32 + 255) / 256, 256>>>();
    // 8) dual GEMM + bias + softplus (mma.sync bf16 3-split + ldmatrix)
    gemm_kernel<<<(VNUM + 63) / 64, 256, GEMM_SMEM>>>(lb, sb, out);
}

// round 17
// speedup vs baseline: 1.0054x; 1.0054x over previous
#include <cuda_runtime.h>
#include <cuda_bf16.h>
#include <cuda_fp16.h>
#include <cstdint>

#define VNUM 50000
#define OUTD 128
#define EMAX 1600000
#define EPS_F 1e-7f
#define PADK 136                       // padded k-stride (bf16 elems) -> conflict-free frags

// ---------------------------------------------------------------------------
// Device-global scratch (no runtime allocation allowed).
// ---------------------------------------------------------------------------
__device__ float g_ptr[(size_t)VNUM * OUTD];   // segment-sum result (25.6 MB)
__device__ int   g_deg[VNUM];
__device__ int   g_off[VNUM + 1];
__device__ int   g_cursor[VNUM];
__device__ int2  g_sw[EMAX];                   // packed (sidx, bitcast(weight))
__device__ __align__(16) __half g_vrh[(size_t)VNUM * OUTD];  // fp16 vrepr (12.8 MB)
// B = [loc_w ; std_w] as 256 rows x 128 k, bf16 hi/lo, row-major.
__device__ __align__(16) __nv_bfloat16 g_Bhi[256 * 128];
__device__ __align__(16) __nv_bfloat16 g_Blo[256 * 128];

// ---------------------------------------------------------------------------
// mma.sync m16n8k16 bf16 (baseline sm_80+ PTX -- no sm_103a features needed)
// ---------------------------------------------------------------------------
__device__ __forceinline__ void mma16816(float* c, const uint32_t* a, const uint32_t* b) {
    asm volatile(
        "mma.sync.aligned.m16n8k16.row.col.f32.bf16.bf16.f32 "
        "{%0,%1,%2,%3}, {%4,%5,%6,%7}, {%8,%9}, {%0,%1,%2,%3};"
        : "+f"(c[0]), "+f"(c[1]), "+f"(c[2]), "+f"(c[3])
        : "r"(a[0]), "r"(a[1]), "r"(a[2]), "r"(a[3]), "r"(b[0]), "r"(b[1]));
}

// ---------------------------------------------------------------------------
// Kernel 1: zero degree counters
// ---------------------------------------------------------------------------
__global__ void zero_deg_kernel() {
    int i = blockIdx.x * blockDim.x + threadIdx.x;
    if (i < VNUM) g_deg[i] = 0;
}

// ---------------------------------------------------------------------------
// Kernel 2: count edges per target, 4 edges per thread (int4 loads, MLP=4)
// ---------------------------------------------------------------------------
__global__ void count_kernel(const int* __restrict__ tidx, int E) {
    int i = (blockIdx.x * blockDim.x + threadIdx.x) * 4;
    if (i + 3 < E) {
        int4 t = __ldg((const int4*)(tidx + i));
        atomicAdd(&g_deg[t.x], 1);
        atomicAdd(&g_deg[t.y], 1);
        atomicAdd(&g_deg[t.z], 1);
        atomicAdd(&g_deg[t.w], 1);
    } else {
        for (int e = i; e < E; e++) atomicAdd(&g_deg[__ldg(tidx + e)], 1);
    }
}

// ---------------------------------------------------------------------------
// Kernel 3: exclusive scan -> g_off, g_cursor. One block, warp-shuffle scan.
// ---------------------------------------------------------------------------
__global__ void scan_kernel() {
    __shared__ int warp_tot[32];
    __shared__ int carry_sh;
    int tid  = threadIdx.x;
    int lane = tid & 31;
    int wid  = tid >> 5;
    if (tid == 0) carry_sh = 0;
    __syncthreads();

    for (int base = 0; base < VNUM; base += 1024) {
        int i = base + tid;
        int x = (i < VNUM) ? g_deg[i] : 0;

        int incl = x;
#pragma unroll
        for (int ofs = 1; ofs < 32; ofs <<= 1) {
            int v = __shfl_up_sync(0xffffffffu, incl, ofs);
            if (lane >= ofs) incl += v;
        }
        if (lane == 31) warp_tot[wid] = incl;
        __syncthreads();

        if (wid == 0) {
            int t = warp_tot[lane];
            int s = t;
#pragma unroll
            for (int ofs = 1; ofs < 32; ofs <<= 1) {
                int v = __shfl_up_sync(0xffffffffu, s, ofs);
                if (lane >= ofs) s += v;
            }
            warp_tot[lane] = s - t;
        }
        __syncthreads();

        int carry = carry_sh;
        int excl = carry + warp_tot[wid] + incl - x;
        if (i < VNUM) {
            g_off[i] = excl;
            g_cursor[i] = excl;
        }
        __syncthreads();
        if (tid == 1023) carry_sh = carry + warp_tot[31] + incl;
        __syncthreads();
    }
    if (tid == 0) g_off[VNUM] = carry_sh;
}

// ---------------------------------------------------------------------------
// Kernel 4: fill CSR slots, 4 edges per thread (vector loads, MLP=4)
// ---------------------------------------------------------------------------
__global__ void fill_kernel(const int* __restrict__ sidx,
                            const int* __restrict__ tidx,
                            const float* __restrict__ enorm,
                            const float* __restrict__ esgn,
                            int E) {
    int i = (blockIdx.x * blockDim.x + threadIdx.x) * 4;
    if (i + 3 < E) {
        int4   s = __ldg((const int4*)(sidx + i));
        int4   t = __ldg((const int4*)(tidx + i));
        float4 n = __ldg((const float4*)(enorm + i));
        float4 g = __ldg((const float4*)(esgn + i));
        int p0 = atomicAdd(&g_cursor[t.x], 1);
        int p1 = atomicAdd(&g_cursor[t.y], 1);
        int p2 = atomicAdd(&g_cursor[t.z], 1);
        int p3 = atomicAdd(&g_cursor[t.w], 1);
        g_sw[p0] = make_int2(s.x, __float_as_int(n.x * g.x));
        g_sw[p1] = make_int2(s.y, __float_as_int(n.y * g.y));
        g_sw[p2] = make_int2(s.z, __float_as_int(n.z * g.z));
        g_sw[p3] = make_int2(s.w, __float_as_int(n.w * g.w));
    } else {
        for (int e = i; e < E; e++) {
            int t = __ldg(tidx + e);
            int pos = atomicAdd(&g_cursor[t], 1);
            float w = __ldg(enorm + e) * __ldg(esgn + e);
            g_sw[pos] = make_int2(__ldg(sidx + e), __float_as_int(w));
        }
    }
}

// ---------------------------------------------------------------------------
// Kernel 5: split weights to bf16 hi/lo, row-major [256][128].
// ---------------------------------------------------------------------------
__global__ void wconv_kernel(const float* __restrict__ lw,
                             const float* __restrict__ sw) {
    int idx = blockIdx.x * blockDim.x + threadIdx.x;
    if (idx >= 256 * 128) return;
    int n = idx >> 7;
    int k = idx & 127;
    float w = (n < 128) ? lw[n * 128 + k] : sw[(n - 128) * 128 + k];
    __nv_bfloat16 hi = __float2bfloat16(w);
    __nv_bfloat16 lo = __float2bfloat16(w - __bfloat162float(hi));
    g_Bhi[idx] = hi;
    g_Blo[idx] = lo;
}

// ---------------------------------------------------------------------------
// Kernel 6: convert vrepr fp32 -> fp16 (halves gather traffic).
// ---------------------------------------------------------------------------
__global__ void vconv_kernel(const float* __restrict__ vrepr) {
    int i = blockIdx.x * blockDim.x + threadIdx.x;
    const int n4 = VNUM * OUTD / 4;
    if (i >= n4) return;
    float4 v = __ldg((const float4*)vrepr + i);
    __half2 h01 = __floats2half2_rn(v.x, v.y);
    __half2 h23 = __floats2half2_rn(v.z, v.w);
    uint2 p;
    p.x = *(uint32_t*)&h01;
    p.y = *(uint32_t*)&h23;
    *((uint2*)g_vrh + i) = p;
}

// ---------------------------------------------------------------------------
// Kernel 7: gather-aggregate. One warp per target row, batched coalesced edge
// loads + shfl broadcast, MLP-4 pipeline. NO scalar tail: invalid lanes carry
// (s=0, w=0.0) so the final partial batch runs the same unrolled path
// (wasted loads hit row 0 in L2 and contribute zero).
// fp16 rows (256 B/edge), fp32 accumulation, one STG.128 per lane.
// ---------------------------------------------------------------------------
__global__ void gather_kernel() {
    int v = (blockIdx.x * blockDim.x + threadIdx.x) >> 5;
    int lane = threadIdx.x & 31;
    if (v >= VNUM) return;

    int beg = __ldg(&g_off[v]);
    int end = __ldg(&g_off[v + 1]);

    float4 acc = make_float4(0.f, 0.f, 0.f, 0.f);
    const uint2* vrh = (const uint2*)g_vrh;    // 32 uint2 per row (4 halves each)
    const unsigned FULL = 0xffffffffu;

    for (int base = beg; base < end; base += 32) {
        int n = end - base;                    // may be <32 on last batch
        int2 rec = (lane < n) ? __ldg(&g_sw[base + lane]) : make_int2(0, 0);

#pragma unroll
        for (int j = 0; j < 32; j += 4) {
            int s0 = __shfl_sync(FULL, rec.x, j);
            int s1 = __shfl_sync(FULL, rec.x, j + 1);
            int s2 = __shfl_sync(FULL, rec.x, j + 2);
            int s3 = __shfl_sync(FULL, rec.x, j + 3);
            float w0 = __int_as_float(__shfl_sync(FULL, rec.y, j));
            float w1 = __int_as_float(__shfl_sync(FULL, rec.y, j + 1));
            float w2 = __int_as_float(__shfl_sync(FULL, rec.y, j + 2));
            float w3 = __int_as_float(__shfl_sync(FULL, rec.y, j + 3));
            uint2 p0 = __ldg(vrh + (size_t)s0 * 32 + lane);
            uint2 p1 = __ldg(vrh + (size_t)s1 * 32 + lane);
            uint2 p2 = __ldg(vrh + (size_t)s2 * 32 + lane);
            uint2 p3 = __ldg(vrh + (size_t)s3 * 32 + lane);
            float2 a01, a23;
            a01 = __half22float2(*(__half2*)&p0.x); a23 = __half22float2(*(__half2*)&p0.y);
            acc.x += w0 * a01.x; acc.y += w0 * a01.y; acc.z += w0 * a23.x; acc.w += w0 * a23.y;
            a01 = __half22float2(*(__half2*)&p1.x); a23 = __half22float2(*(__half2*)&p1.y);
            acc.x += w1 * a01.x; acc.y += w1 * a01.y; acc.z += w1 * a23.x; acc.w += w1 * a23.y;
            a01 = __half22float2(*(__half2*)&p2.x); a23 = __half22float2(*(__half2*)&p2.y);
            acc.x += w2 * a01.x; acc.y += w2 * a01.y; acc.z += w2 * a23.x; acc.w += w2 * a23.y;
            a01 = __half22float2(*(__half2*)&p3.x); a23 = __half22float2(*(__half2*)&p3.y);
            acc.x += w3 * a01.x; acc.y += w3 * a01.y; acc.z += w3 * a23.x; acc.w += w3 * a23.y;
        }
    }
    ((float4*)g_ptr)[(size_t)v * 32 + lane] = acc;
}

// ---------------------------------------------------------------------------
// Kernel 8: dual GEMM + bias + softplus via mma.sync bf16 3-split.
//   D = Ahi*Bhi + Alo*Bhi + Ahi*Blo   (error ~2^-16)
// Block: 256 threads / 8 warps, 64 rows x 256 cols (N=256 = loc|std).
// (R15-proven manual fragment loads.)
// ---------------------------------------------------------------------------
#define SM_AHI 0
#define SM_ALO (64 * PADK * 2)                     // 17408
#define SM_BHI (2 * 64 * PADK * 2)                 // 34816
#define SM_BLO (2 * 64 * PADK * 2 + 256 * PADK * 2)// 104448
#define GEMM_SMEM (2 * 64 * PADK * 2 + 2 * 256 * PADK * 2)  // 174080

__global__ void __launch_bounds__(256, 1)
gemm_kernel(const float* __restrict__ lb,
            const float* __restrict__ sb,
            float* __restrict__ out) {
    extern __shared__ __align__(16) uint8_t smem[];
    __nv_bfloat16* shAhi = (__nv_bfloat16*)(smem + SM_AHI);
    __nv_bfloat16* shAlo = (__nv_bfloat16*)(smem + SM_ALO);
    __nv_bfloat16* shBhi = (__nv_bfloat16*)(smem + SM_BHI);
    __nv_bfloat16* shBlo = (__nv_bfloat16*)(smem + SM_BLO);

    int tid = threadIdx.x;
    int row0 = blockIdx.x * 64;

    // Stage A: read fp32 g_ptr, split into bf16 hi/lo.
    for (int i = tid; i < 2048; i += 256) {
        int r = i >> 5;
        int c4 = i & 31;
        int row = row0 + r;
        float4 v = (row < VNUM) ? __ldg((const float4*)g_ptr + (size_t)row * 32 + c4)
                                : make_float4(0.f, 0.f, 0.f, 0.f);
        __nv_bfloat16 h0 = __float2bfloat16(v.x), h1 = __float2bfloat16(v.y);
        __nv_bfloat16 h2 = __float2bfloat16(v.z), h3 = __float2bfloat16(v.w);
        __nv_bfloat16 l0 = __float2bfloat16(v.x - __bfloat162float(h0));
        __nv_bfloat16 l1 = __float2bfloat16(v.y - __bfloat162float(h1));
        __nv_bfloat16 l2 = __float2bfloat16(v.z - __bfloat162float(h2));
        __nv_bfloat16 l3 = __float2bfloat16(v.w - __bfloat162float(h3));
        uint2 hp, lp;
        hp.x = (uint32_t)__bfloat16_as_ushort(h0) | ((uint32_t)__bfloat16_as_ushort(h1) << 16);
        hp.y = (uint32_t)__bfloat16_as_ushort(h2) | ((uint32_t)__bfloat16_as_ushort(h3) << 16);
        lp.x = (uint32_t)__bfloat16_as_ushort(l0) | ((uint32_t)__bfloat16_as_ushort(l1) << 16);
        lp.y = (uint32_t)__bfloat16_as_ushort(l2) | ((uint32_t)__bfloat16_as_ushort(l3) << 16);
        *(uint2*)(shAhi + r * PADK + c4 * 4) = hp;
        *(uint2*)(shAlo + r * PADK + c4 * 4) = lp;
    }
    // Stage B: 256 rows x 16 uint4 (8 bf16 each) per matrix.
    for (int i = tid; i < 4096; i += 256) {
        int n = i >> 4;
        int c8 = i & 15;
        *(uint4*)(shBhi + n * PADK + c8 * 8) = *((const uint4*)g_Bhi + (size_t)n * 16 + c8);
        *(uint4*)(shBlo + n * PADK + c8 * 8) = *((const uint4*)g_Blo + (size_t)n * 16 + c8);
    }
    __syncthreads();

    int warp = tid >> 5;
    int lane = tid & 31;
    int warp_m = warp & 3;
    int col_half = warp >> 2;
    int g = lane >> 2;
    int tg = lane & 3;

    const __nv_bfloat16* Ah = shAhi + (warp_m * 16 + g) * PADK;
    const __nv_bfloat16* Al = shAlo + (warp_m * 16 + g) * PADK;

    float acc[16][4];
#pragma unroll
    for (int t = 0; t < 16; t++)
        acc[t][0] = acc[t][1] = acc[t][2] = acc[t][3] = 0.f;

#pragma unroll
    for (int ks = 0; ks < 8; ks++) {
        int k0 = ks * 16 + tg * 2;
        uint32_t ah[4], al[4];
        ah[0] = *(const uint32_t*)(Ah + k0);
        ah[1] = *(const uint32_t*)(Ah + 8 * PADK + k0);
        ah[2] = *(const uint32_t*)(Ah + k0 + 8);
        ah[3] = *(const uint32_t*)(Ah + 8 * PADK + k0 + 8);
        al[0] = *(const uint32_t*)(Al + k0);
        al[1] = *(const uint32_t*)(Al + 8 * PADK + k0);
        al[2] = *(const uint32_t*)(Al + k0 + 8);
        al[3] = *(const uint32_t*)(Al + 8 * PADK + k0 + 8);

#pragma unroll
        for (int nt = 0; nt < 16; nt++) {
            int n = col_half * 128 + nt * 8 + g;
            const __nv_bfloat16* Bh = shBhi + n * PADK;
            const __nv_bfloat16* Bl = shBlo + n * PADK;
            uint32_t bh[2], bl[2];
            bh[0] = *(const uint32_t*)(Bh + k0);
            bh[1] = *(const uint32_t*)(Bh + k0 + 8);
            bl[0] = *(const uint32_t*)(Bl + k0);
            bl[1] = *(const uint32_t*)(Bl + k0 + 8);
            mma16816(acc[nt], ah, bh);
            mma16816(acc[nt], al, bh);
            mma16816(acc[nt], ah, bl);
        }
    }

    int row_a = row0 + warp_m * 16 + g;
    int row_b = row_a + 8;
    float* out_loc = out;
    float* out_std = out + (size_t)VNUM * OUTD;

#pragma unroll
    for (int nt = 0; nt < 16; nt++) {
        int ncol = col_half * 128 + nt * 8 + tg * 2;
        if (ncol < 128) {
            float b0 = __ldg(lb + ncol), b1 = __ldg(lb + ncol + 1);
            if (row_a < VNUM) {
                float2 o = make_float2(acc[nt][0] + b0, acc[nt][1] + b1);
                *(float2*)(out_loc + (size_t)row_a * OUTD + ncol) = o;
            }
            if (row_b < VNUM) {
                float2 o = make_float2(acc[nt][2] + b0, acc[nt][3] + b1);
                *(float2*)(out_loc + (size_t)row_b * OUTD + ncol) = o;
            }
        } else {
            int sc = ncol - 128;
            float b0 = __ldg(sb + sc), b1 = __ldg(sb + sc + 1);
            if (row_a < VNUM) {
                float x0 = acc[nt][0] + b0, x1 = acc[nt][1] + b1;
                float2 o;
                o.x = fmaxf(x0, 0.f) + log1pf(expf(-fabsf(x0))) + EPS_F;
                o.y = fmaxf(x1, 0.f) + log1pf(expf(-fabsf(x1))) + EPS_F;
                *(float2*)(out_std + (size_t)row_a * OUTD + sc) = o;
            }
            if (row_b < VNUM) {
                float x0 = acc[nt][2] + b0, x1 = acc[nt][3] + b1;
                float2 o;
                o.x = fmaxf(x0, 0.f) + log1pf(expf(-fabsf(x0))) + EPS_F;
                o.y = fmaxf(x1, 0.f) + log1pf(expf(-fabsf(x1))) + EPS_F;
                *(float2*)(out_std + (size_t)row_b * OUTD + sc) = o;
            }
        }
    }
}

// ---------------------------------------------------------------------------
// Launch. Inputs: sidx, tidx, enorm, esgn, vrepr, loc_w, loc_b, std_w, std_b
// Output: [loc (VNUM*128), std (VNUM*128)] fp32
// ---------------------------------------------------------------------------
extern "C" void kernel_launch(void* const* d_in, const int* in_sizes, int n_in,
                              void* d_out, int out_size) {
    const int*   sidx  = (const int*)d_in[0];
    const int*   tidx  = (const int*)d_in[1];
    const float* enorm = (const float*)d_in[2];
    const float* esgn  = (const float*)d_in[3];
    const float* vrepr = (const float*)d_in[4];
    const float* lw    = (const float*)d_in[5];
    const float* lb    = (const float*)d_in[6];
    const float* sw    = (const float*)d_in[7];
    const float* sb    = (const float*)d_in[8];
    float* out = (float*)d_out;
    int E = in_sizes[0];
    if (E > EMAX) E = EMAX;

    (void)cudaFuncSetAttribute(gemm_kernel,
                               cudaFuncAttributeMaxDynamicSharedMemorySize, GEMM_SMEM);

    // 1) zero degree counters
    zero_deg_kernel<<<(VNUM + 255) / 256, 256>>>();
    // 2) count edges per target (4/thread)
    count_kernel<<<((E + 3) / 4 + 255) / 256, 256>>>(tidx, E);
    // 3) exclusive scan -> CSR offsets + cursors
    scan_kernel<<<1, 1024>>>();
    // 4) fill CSR (4/thread)
    fill_kernel<<<((E + 3) / 4 + 255) / 256, 256>>>(sidx, tidx, enorm, esgn, E);
    // 5) weights -> bf16 hi/lo
    wconv_kernel<<<(256 * 128 + 255) / 256, 256>>>(lw, sw);
    // 6) vrepr -> fp16
    vconv_kernel<<<(VNUM * OUTD / 4 + 255) / 256, 256>>>(vrepr);
    // 7) gather-aggregate (fp16 rows, MLP-4, no scalar tail) -> fp32 ptr
    gather_kernel<<<(VNUM * 32 + 255) / 256, 256>>>();
    // 8) dual GEMM + bias + softplus (mma.sync bf16 3-split)
    gemm_kernel<<<(VNUM + 63) / 64, 256, GEMM_SMEM>>>(lb, sb, out);
}